// round 15
// baseline (speedup 1.0000x reference)
#include <cuda_runtime.h>
#include <cuda_fp16.h>
#include <cstdint>

// Grouped submanifold sparse conv, N=400000, C_IN=C_OUT=64, GROUPS=4, K=27.
// R15: pipeline-depth round. R9-R14 all plateau at 254-260us with warps
// stalled ~90% of wall time regardless of L1/issue levels; ~40% of gather
// rows miss L2 (DRAM ~400MB/run) and every variant had only ~1-2 consume-
// waves (~400-800cyc) of async window -- less than congested DRAM latency.
// Fix: 16-slot ring = 4 waves of 4 bodies in flight (cp.async.wait_group 3),
// window ~3 consume-waves (~1500cyc). Funded by VPW=16 + half2 weights.

#define KOFF 27
#define VPW  16
#define NWARPS 16
#define THREADS (NWARPS * 32)
#define WAVE 4
#define NWAVES 4
#define NSLOT (NWAVES * WAVE)           // 16 slots x 256 B per warp
// half2 weight area: wh[g*PGH + k*128 + q*8 + cp]
//   q 0..15: q<8 -> X (even co), q>=8 -> Y (odd co)
//   pair = (w[g][k][2q'][co], w[g][k][2q'+1][co]), q'=q&7, co=2cp+(q>>3)
#define PGH   (KOFF * 128 + 8)          // 3464 words per group
#define W_WORDS (4 * PGH)               // 13856 words = 55,424 B
#define ACC_F   W_WORDS
#define ACC_PER_WARP (VPW * 32 * 2)     // 1024 floats = 4 KB
#define RING_F  (ACC_F + NWARPS * ACC_PER_WARP)
#define RING_PER_WARP (NSLOT * 64)      // 1024 floats = 4 KB
#define LIST_F  (RING_F + NWARPS * RING_PER_WARP)
#define LIST_CAP (VPW * KOFF)           // 432 entries
#define SMEM_WORDS (LIST_F + NWARPS * LIST_CAP)
#define SMEM_BYTES (SMEM_WORDS * 4)     // 211,456 B
#define FULL 0xffffffffu

#define CP_ASYNC16(dst, src) \
    asm volatile("cp.async.cg.shared.global [%0], [%1], 16;" \
                 :: "r"(dst), "l"(src) : "memory")
#define CP_COMMIT() asm volatile("cp.async.commit_group;" ::: "memory")
#define CP_WAIT3()  asm volatile("cp.async.wait_group 3;" ::: "memory")
#define CP_WAIT0()  asm volatile("cp.async.wait_group 0;" ::: "memory")

#define FMA2(d, a, b, c) \
    asm("fma.rn.f32x2 %0, %1, %2, %3;" : "=l"(d) : "l"(a), "l"(b), "l"(c))
#define MUL2(d, a, b) \
    asm("mul.rn.f32x2 %0, %1, %2;" : "=l"(d) : "l"(a), "l"(b))

__device__ __forceinline__ unsigned long long pk2(float a, float b) {
    unsigned long long r;
    asm("mov.b64 %0, {%1, %2};" : "=l"(r) : "f"(a), "f"(b));
    return r;
}
__device__ __forceinline__ void upk2(unsigned long long v, float& a, float& b) {
    asm("mov.b64 {%0, %1}, %2;" : "=f"(a), "=f"(b) : "l"(v));
}

__global__ __launch_bounds__(THREADS, 1)
void subm_conv_r15(const float* __restrict__ feat,
                   const float* __restrict__ weight,
                   const float* __restrict__ bias,
                   const int* __restrict__ nb,
                   float* __restrict__ out,
                   int N, int total_iters, int totwarps)
{
    extern __shared__ float sm[];
    __half2* wh = (__half2*)sm;

    // Stage weights as ci-pair half2: i = ((g*27 + k)*16 + q)*8 + cp
    for (int i = threadIdx.x; i < 4 * KOFF * 128; i += THREADS) {
        int cp = i & 7;
        int q  = (i >> 3) & 15;
        int gk = i >> 7;                 // g*27 + k
        int g  = gk / KOFF;
        int k  = gk - g * KOFF;
        int ci0 = (q & 7) * 2;
        int co  = 2 * cp + (q >> 3);
        const float* wsrc = weight + ((size_t)gk * 16 + ci0) * 16 + co;
        wh[g * PGH + k * 128 + q * 8 + cp] =
            __floats2half2_rn(wsrc[0], wsrc[16]);
    }
    __syncthreads();

    const int lane = threadIdx.x & 31;
    const int wid  = threadIdx.x >> 5;
    const int g    = lane >> 3;          // group
    const int cp   = lane & 7;           // co-pair within group
    const float bx = bias[2 * lane];
    const float by = bias[2 * lane + 1];
    const __half2* whbase = wh + g * PGH + cp;

    float2*   accw  = (float2*)(sm + ACC_F) + wid * (VPW * 32);
    float*    ringw = sm + RING_F + wid * RING_PER_WARP;
    uint32_t* lw    = (uint32_t*)(sm + LIST_F) + wid * LIST_CAP;
    const uint32_t ring_u32 = (uint32_t)__cvta_generic_to_shared(ringw);

    for (int it = blockIdx.x * NWARPS + wid; it < total_iters; it += totwarps) {
        const int vb = it * VPW;
        const int* nbrow = nb + (size_t)vb * KOFF;

        // ---- Phase A: activity mask, prefix scan, emit list (k-major) ----
        unsigned am = 0;
        #pragma unroll
        for (int j = 0; j < VPW; ++j) {
            int v = vb + j;
            int id = (lane < KOFF && v < N) ? nbrow[j * KOFF + lane] : -1;
            am |= (id >= 0 ? 1u : 0u) << j;
        }
        int pc = __popc(am);
        int s = pc;
        #pragma unroll
        for (int d = 1; d < 32; d <<= 1) {
            int t = __shfl_up_sync(FULL, s, d);
            if (lane >= d) s += t;
        }
        const int nb_total = __shfl_sync(FULL, s, 31);
        int pos = s - pc;                 // exclusive prefix; lane = k
        unsigned em = am;
        while (em) {                      // re-read nb row (warm): no idx[]
            int j = __ffs(em) - 1; em &= em - 1;
            uint32_t ni = (uint32_t)nbrow[j * KOFF + lane];
            lw[pos++] = (ni << 10) | (uint32_t)(j << 5) | (uint32_t)lane;
        }
        #pragma unroll
        for (int j = 0; j < VPW; ++j)
            accw[j * 32 + lane] = make_float2(bx, by);
        __syncwarp();

        // ---- async fill: wave of 4 bodies, 2 per instruction, LDS-only ----
        auto fill = [&](int wbase, int slotbase) {
            #pragma unroll
            for (int p = 0; p < WAVE; p += 2) {
                int bi = wbase + p + (lane >> 4);
                if (bi < nb_total) {
                    uint32_t ni = lw[bi] >> 10;
                    uint32_t dst = ring_u32
                                 + (uint32_t)(slotbase + p + (lane >> 4)) * 256u
                                 + (uint32_t)(lane & 15) * 16u;
                    const float* src = feat + (size_t)ni * 64 + (lane & 15) * 4;
                    CP_ASYNC16(dst, src);
                }
            }
            CP_COMMIT();
        };

        // Prime 4 waves (depth-4 pipeline).
        #pragma unroll
        for (int w = 0; w < NWAVES; ++w) fill(w * WAVE, w * WAVE);

        // ---- Phase B: dense consume, 3 waves always in flight ----
        unsigned long long wx[8], wy[8];
        int kcur = -1;
        for (int wbase = 0; wbase < nb_total; wbase += WAVE) {
            CP_WAIT3();                   // wave (wbase/WAVE) complete
            __syncwarp();
            const int slotbase = ((wbase >> 2) & (NWAVES - 1)) * WAVE;
            const int cend = (wbase + WAVE < nb_total) ? wbase + WAVE : nb_total;
            for (int i = wbase; i < cend; ++i) {
                const uint32_t e = lw[i];               // warp-uniform
                const int k = (int)(e & 31u);
                const int j = (int)((e >> 5) & 31u);
                if (k != kcur) {                        // ~1 per 3.66 bodies
                    kcur = k;
                    const __half2* wp = whbase + k * 128;
                    #pragma unroll
                    for (int q = 0; q < 8; ++q) {
                        float2 fx = __half22float2(wp[q * 8]);
                        wx[q] = pk2(fx.x, fx.y);
                    }
                    #pragma unroll
                    for (int q = 0; q < 8; ++q) {
                        float2 fy = __half22float2(wp[(8 + q) * 8]);
                        wy[q] = pk2(fy.x, fy.y);
                    }
                }
                const ulonglong2* sp = (const ulonglong2*)
                    (ringw + (slotbase + (i - wbase)) * 64 + g * 16);
                ulonglong2 p0 = sp[0], p1 = sp[1], p2 = sp[2], p3 = sp[3];
                unsigned long long ax, ay;
                MUL2(ax, p0.x, wx[0]);        MUL2(ay, p0.x, wy[0]);
                FMA2(ax, p0.y, wx[1], ax);    FMA2(ay, p0.y, wy[1], ay);
                FMA2(ax, p1.x, wx[2], ax);    FMA2(ay, p1.x, wy[2], ay);
                FMA2(ax, p1.y, wx[3], ax);    FMA2(ay, p1.y, wy[3], ay);
                FMA2(ax, p2.x, wx[4], ax);    FMA2(ay, p2.x, wy[4], ay);
                FMA2(ax, p2.y, wx[5], ax);    FMA2(ay, p2.y, wy[5], ay);
                FMA2(ax, p3.x, wx[6], ax);    FMA2(ay, p3.x, wy[6], ay);
                FMA2(ax, p3.y, wx[7], ax);    FMA2(ay, p3.y, wy[7], ay);
                float x0, x1, y0, y1;
                upk2(ax, x0, x1);
                upk2(ay, y0, y1);
                float xs = x0 + x1, ys = y0 + y1;
                float2* ap = accw + j * 32 + lane;      // same-lane RMW
                float2 a = *ap;
                a.x += xs; a.y += ys;
                *ap = a;
            }
            fill(wbase + NWAVES * WAVE, slotbase);      // refill freed wave
        }
        CP_WAIT0();
        __syncwarp();

        // ---- store 16 voxels x 64 channels ----
        #pragma unroll
        for (int j = 0; j < VPW; ++j) {
            int v = vb + j;
            if (v < N)
                ((float2*)(out + (size_t)v * 64))[lane] = accw[j * 32 + lane];
        }
        __syncwarp();
    }
}

extern "C" void kernel_launch(void* const* d_in, const int* in_sizes, int n_in,
                              void* d_out, int out_size)
{
    const float* feat   = (const float*)d_in[0];  // [N, 64]
    const float* weight = (const float*)d_in[1];  // [4, 27, 16, 16]
    const float* bias   = (const float*)d_in[2];  // [64]
    const int*   nb     = (const int*)d_in[3];    // [N, 27]
    float* out = (float*)d_out;

    int N = in_sizes[0] / 64;

    // Idempotent, enqueues no work; safe under graph capture.
    cudaFuncSetAttribute(subm_conv_r15,
                         cudaFuncAttributeMaxDynamicSharedMemorySize, SMEM_BYTES);

    const int blocks = 152;              // 1 CTA/SM (211.5 KB smem)
    const int totwarps = blocks * NWARPS;
    int total_iters = (N + VPW - 1) / VPW;

    subm_conv_r15<<<blocks, THREADS, SMEM_BYTES>>>(feat, weight, bias, nb,
                                                   out, N, total_iters, totwarps);
    (void)n_in; (void)out_size;
}

// round 16
// speedup vs baseline: 1.0241x; 1.0241x over previous
#include <cuda_runtime.h>
#include <cuda_fp16.h>
#include <cstdint>

// Grouped submanifold sparse conv, N=400000, C_IN=C_OUT=64, GROUPS=4, K=27.
// R16: break the per-body serial chain (LDS 29 -> FMA2 chain -> acc LDS 29)
// that capped every R9-R15 variant at ~254us. Every k-run in the body list
// is padded to EVEN length (dummy: same k, scratch acc row j=VPW, gather
// skipped), so the consume loop processes guaranteed same-k PAIRS:
// one weight-reload check per pair, 4 independent FMA2 chains, 2 independent
// ring loads, 2 hazard-free acc RMWs -> ~2x per-warp ILP for +13.7% bodies.

#define KOFF 27
#define VPW  16
#define NWARPS 16
#define THREADS (NWARPS * 32)
#define WAVE 4
#define NSLOT (2 * WAVE)                // 8 slots x 256 B (depth-2, best)
// half2 weight area: wh[g*PGH + k*128 + q*8 + cp]
#define PGH   (KOFF * 128 + 8)          // 3464 words per group
#define W_WORDS (4 * PGH)               // 55,424 B
#define ACC_F   W_WORDS
#define ACC_ROWS (VPW + 1)              // +1 scratch row for dummies
#define ACC_PER_WARP (ACC_ROWS * 32 * 2)  // 1088 floats = 4.25 KB
#define RING_F  (ACC_F + NWARPS * ACC_PER_WARP)
#define RING_PER_WARP (NSLOT * 64)      // 512 floats = 2 KB
#define LIST_F  (RING_F + NWARPS * RING_PER_WARP)
#define LIST_CAP 464                    // 432 max real + <=27 dummies, 16B mult
#define SMEM_WORDS (LIST_F + NWARPS * LIST_CAP)
#define SMEM_BYTES (SMEM_WORDS * 4)     // 185,216 B
#define FULL 0xffffffffu

#define CP_ASYNC16(dst, src) \
    asm volatile("cp.async.cg.shared.global [%0], [%1], 16;" \
                 :: "r"(dst), "l"(src) : "memory")
#define CP_COMMIT() asm volatile("cp.async.commit_group;" ::: "memory")
#define CP_WAIT1()  asm volatile("cp.async.wait_group 1;" ::: "memory")
#define CP_WAIT0()  asm volatile("cp.async.wait_group 0;" ::: "memory")

#define FMA2(d, a, b, c) \
    asm("fma.rn.f32x2 %0, %1, %2, %3;" : "=l"(d) : "l"(a), "l"(b), "l"(c))
#define MUL2(d, a, b) \
    asm("mul.rn.f32x2 %0, %1, %2;" : "=l"(d) : "l"(a), "l"(b))

__device__ __forceinline__ unsigned long long pk2(float a, float b) {
    unsigned long long r;
    asm("mov.b64 %0, {%1, %2};" : "=l"(r) : "f"(a), "f"(b));
    return r;
}
__device__ __forceinline__ void upk2(unsigned long long v, float& a, float& b) {
    asm("mov.b64 {%0, %1}, %2;" : "=f"(a), "=f"(b) : "l"(v));
}

__global__ __launch_bounds__(THREADS, 1)
void subm_conv_r16(const float* __restrict__ feat,
                   const float* __restrict__ weight,
                   const float* __restrict__ bias,
                   const int* __restrict__ nb,
                   float* __restrict__ out,
                   int N, int total_iters, int totwarps)
{
    extern __shared__ float sm[];
    __half2* wh = (__half2*)sm;

    // Stage weights as ci-pair half2: i = ((g*27 + k)*16 + q)*8 + cp
    for (int i = threadIdx.x; i < 4 * KOFF * 128; i += THREADS) {
        int cp = i & 7;
        int q  = (i >> 3) & 15;
        int gk = i >> 7;
        int g  = gk / KOFF;
        int k  = gk - g * KOFF;
        int ci0 = (q & 7) * 2;
        int co  = 2 * cp + (q >> 3);
        const float* wsrc = weight + ((size_t)gk * 16 + ci0) * 16 + co;
        wh[g * PGH + k * 128 + q * 8 + cp] =
            __floats2half2_rn(wsrc[0], wsrc[16]);
    }
    __syncthreads();

    const int lane = threadIdx.x & 31;
    const int wid  = threadIdx.x >> 5;
    const int g    = lane >> 3;          // group
    const int cp   = lane & 7;           // co-pair within group
    const float bx = bias[2 * lane];
    const float by = bias[2 * lane + 1];
    const __half2* whbase = wh + g * PGH + cp;

    float2*   accw  = (float2*)(sm + ACC_F) + wid * (ACC_ROWS * 32);
    float*    ringw = sm + RING_F + wid * RING_PER_WARP;
    uint32_t* lw    = (uint32_t*)(sm + LIST_F) + wid * LIST_CAP;
    const uint32_t ring_u32 = (uint32_t)__cvta_generic_to_shared(ringw);

    for (int it = blockIdx.x * NWARPS + wid; it < total_iters; it += totwarps) {
        const int vb = it * VPW;
        const int* nbrow = nb + (size_t)vb * KOFF;

        // ---- Phase A: activity mask; per-run EVEN padding; scan; emit ----
        unsigned am = 0;
        #pragma unroll
        for (int j = 0; j < VPW; ++j) {
            int v = vb + j;
            int id = (lane < KOFF && v < N) ? nbrow[j * KOFF + lane] : -1;
            am |= (id >= 0 ? 1u : 0u) << j;
        }
        int pc = __popc(am);
        int pcp = pc + (pc & 1);         // pad each run to even length
        int s = pcp;
        #pragma unroll
        for (int d = 1; d < 32; d <<= 1) {
            int t = __shfl_up_sync(FULL, s, d);
            if (lane >= d) s += t;
        }
        const int nb_total = __shfl_sync(FULL, s, 31);   // even
        int pos = s - pcp;                // exclusive prefix; lane = k
        unsigned em = am;
        while (em) {                      // emit real bodies (re-read hot nb)
            int j = __ffs(em) - 1; em &= em - 1;
            uint32_t ni = (uint32_t)nbrow[j * KOFF + lane];
            lw[pos++] = (ni << 10) | (uint32_t)(j << 5) | (uint32_t)lane;
        }
        if (pc & 1)                       // dummy: same k, scratch row j=VPW
            lw[pos] = ((uint32_t)vb << 10) | ((uint32_t)VPW << 5)
                    | (uint32_t)lane;
        #pragma unroll
        for (int j = 0; j < ACC_ROWS; ++j)
            accw[j * 32 + lane] = make_float2(bx, by);
        __syncwarp();

        // ---- async fill: wave of 4 bodies, dummies skipped ----
        auto fill = [&](int wbase, int slotbase) {
            #pragma unroll
            for (int p = 0; p < WAVE; p += 2) {
                int bi = wbase + p + (lane >> 4);
                if (bi < nb_total) {
                    uint32_t e = lw[bi];
                    if (((e >> 5) & 31u) != (uint32_t)VPW) {   // not dummy
                        uint32_t ni = e >> 10;
                        uint32_t dst = ring_u32
                            + (uint32_t)(slotbase + p + (lane >> 4)) * 256u
                            + (uint32_t)(lane & 15) * 16u;
                        const float* src =
                            feat + (size_t)ni * 64 + (lane & 15) * 4;
                        CP_ASYNC16(dst, src);
                    }
                }
            }
            CP_COMMIT();
        };

        fill(0, 0);
        fill(WAVE, WAVE);

        // ---- Phase B: consume PAIRS (guaranteed same k) ----
        unsigned long long wx[8], wy[8];
        int kcur = -1;
        for (int wbase = 0; wbase < nb_total; wbase += WAVE) {
            CP_WAIT1();
            __syncwarp();
            const int slotbase = ((wbase >> 2) & 1) * WAVE;
            const int cend = (wbase + WAVE < nb_total) ? wbase + WAVE : nb_total;
            for (int i = wbase; i < cend; i += 2) {
                const uint32_t e0 = lw[i];
                const uint32_t e1 = lw[i + 1];
                const int k  = (int)(e0 & 31u);          // == e1's k
                const int j0 = (int)((e0 >> 5) & 31u);
                const int j1 = (int)((e1 >> 5) & 31u);   // j0 != j1 in-run
                if (k != kcur) {                         // once per pair max
                    kcur = k;
                    const __half2* wp = whbase + k * 128;
                    #pragma unroll
                    for (int q = 0; q < 8; ++q) {
                        float2 fx = __half22float2(wp[q * 8]);
                        wx[q] = pk2(fx.x, fx.y);
                    }
                    #pragma unroll
                    for (int q = 0; q < 8; ++q) {
                        float2 fy = __half22float2(wp[(8 + q) * 8]);
                        wy[q] = pk2(fy.x, fy.y);
                    }
                }
                const int sb = slotbase + (i - wbase);
                const ulonglong2* sA = (const ulonglong2*)
                    (ringw + sb * 64 + g * 16);
                const ulonglong2* sB = (const ulonglong2*)
                    (ringw + (sb + 1) * 64 + g * 16);
                ulonglong2 a0 = sA[0], a1 = sA[1], a2 = sA[2], a3 = sA[3];
                ulonglong2 b0 = sB[0], b1 = sB[1], b2 = sB[2], b3 = sB[3];
                unsigned long long ax0, ay0, ax1, ay1;   // 4 indep chains
                MUL2(ax0, a0.x, wx[0]);       MUL2(ay0, a0.x, wy[0]);
                MUL2(ax1, b0.x, wx[0]);       MUL2(ay1, b0.x, wy[0]);
                FMA2(ax0, a0.y, wx[1], ax0);  FMA2(ay0, a0.y, wy[1], ay0);
                FMA2(ax1, b0.y, wx[1], ax1);  FMA2(ay1, b0.y, wy[1], ay1);
                FMA2(ax0, a1.x, wx[2], ax0);  FMA2(ay0, a1.x, wy[2], ay0);
                FMA2(ax1, b1.x, wx[2], ax1);  FMA2(ay1, b1.x, wy[2], ay1);
                FMA2(ax0, a1.y, wx[3], ax0);  FMA2(ay0, a1.y, wy[3], ay0);
                FMA2(ax1, b1.y, wx[3], ax1);  FMA2(ay1, b1.y, wy[3], ay1);
                FMA2(ax0, a2.x, wx[4], ax0);  FMA2(ay0, a2.x, wy[4], ay0);
                FMA2(ax1, b2.x, wx[4], ax1);  FMA2(ay1, b2.x, wy[4], ay1);
                FMA2(ax0, a2.y, wx[5], ax0);  FMA2(ay0, a2.y, wy[5], ay0);
                FMA2(ax1, b2.y, wx[5], ax1);  FMA2(ay1, b2.y, wy[5], ay1);
                FMA2(ax0, a3.x, wx[6], ax0);  FMA2(ay0, a3.x, wy[6], ay0);
                FMA2(ax1, b3.x, wx[6], ax1);  FMA2(ay1, b3.x, wy[6], ay1);
                FMA2(ax0, a3.y, wx[7], ax0);  FMA2(ay0, a3.y, wy[7], ay0);
                FMA2(ax1, b3.y, wx[7], ax1);  FMA2(ay1, b3.y, wy[7], ay1);
                float u0, u1, v0, v1, u2, u3, v2, v3;
                upk2(ax0, u0, u1);  upk2(ay0, v0, v1);
                upk2(ax1, u2, u3);  upk2(ay1, v2, v3);
                float xs0 = u0 + u1, ys0 = v0 + v1;
                float xs1 = u2 + u3, ys1 = v2 + v3;
                float2* ap0 = accw + j0 * 32 + lane;     // j0 != j1: no hazard
                float2* ap1 = accw + j1 * 32 + lane;
                float2 c0 = *ap0, c1 = *ap1;
                c0.x += xs0; c0.y += ys0;
                c1.x += xs1; c1.y += ys1;
                *ap0 = c0;
                *ap1 = c1;
            }
            fill(wbase + 2 * WAVE, slotbase);
        }
        CP_WAIT0();
        __syncwarp();

        // ---- store 16 voxels x 64 channels (scratch row not stored) ----
        #pragma unroll
        for (int j = 0; j < VPW; ++j) {
            int v = vb + j;
            if (v < N)
                ((float2*)(out + (size_t)v * 64))[lane] = accw[j * 32 + lane];
        }
        __syncwarp();
    }
}

extern "C" void kernel_launch(void* const* d_in, const int* in_sizes, int n_in,
                              void* d_out, int out_size)
{
    const float* feat   = (const float*)d_in[0];  // [N, 64]
    const float* weight = (const float*)d_in[1];  // [4, 27, 16, 16]
    const float* bias   = (const float*)d_in[2];  // [64]
    const int*   nb     = (const int*)d_in[3];    // [N, 27]
    float* out = (float*)d_out;

    int N = in_sizes[0] / 64;

    // Idempotent, enqueues no work; safe under graph capture.
    cudaFuncSetAttribute(subm_conv_r16,
                         cudaFuncAttributeMaxDynamicSharedMemorySize, SMEM_BYTES);

    const int blocks = 152;              // 1 CTA/SM (185.2 KB smem)
    const int totwarps = blocks * NWARPS;
    int total_iters = (N + VPW - 1) / VPW;

    subm_conv_r16<<<blocks, THREADS, SMEM_BYTES>>>(feat, weight, bias, nb,
                                                   out, N, total_iters, totwarps);
    (void)n_in; (void)out_size;
}

// round 17
// speedup vs baseline: 1.0700x; 1.0448x over previous
#include <cuda_runtime.h>
#include <cstdint>

// Grouped submanifold sparse conv, N=400000, C_IN=C_OUT=64, GROUPS=4, K=27.
// R17 = R12 (best: fp32 ci-pair weights in smem, FMA2, k-major body list
// with embedded ni, LDS-only cp.async fill, smem acc RMW, VPW=16, 15 warps)
// + L2 eviction policy: out stores via __stcs and nb reads via __ldcs
// (evict-first). Rationale: smem carveout leaves ~4KB L1, and the out/nb
// streams (145MB, zero reuse) were evicting the 102MB feature array out of
// the 126MB L2 -> ~40% of gathers missed to DRAM (~400 serial ~600-1000cyc
// exposures per warp = the 254us plateau). With feat L2-resident, every
// gather is a ~250cyc L2 hit, fully covered by the depth-2 ring.

#define KOFF 27
#define VPW  16
#define NWARPS 15
#define THREADS (NWARPS * 32)
#define WAVE 4
#define NSLOT (2 * WAVE)                // 8 slots x 256 B per warp
// fp32-pair weight area: ws2[g*PGF2 + k*128 + q*8 + cp] (float2)
//   q in 0..15: q<8 -> X block (even co), q>=8 -> Y block (odd co)
//   pair = (w[g][k][2q'][co], w[g][k][2q'+1][co]), q'=q&7, co=2cp+(q>>3)
#define PGF2  (KOFF * 128 + 8)          // 3464 float2 per group
#define W_FLOATS (4 * PGF2 * 2)         // 27712 floats = 110,848 B
#define ACC_F   W_FLOATS
#define ACC_PER_WARP (VPW * 32 * 2)     // 1024 floats = 4 KB
#define RING_F  (ACC_F + NWARPS * ACC_PER_WARP)
#define RING_PER_WARP (NSLOT * 64)      // 512 floats = 2 KB
#define LIST_F  (RING_F + NWARPS * RING_PER_WARP)
#define LIST_CAP 432                    // = VPW * 27
#define SMEM_WORDS (LIST_F + NWARPS * LIST_CAP)
#define SMEM_BYTES (SMEM_WORDS * 4)     // 228,928 B
#define FULL 0xffffffffu

#define CP_ASYNC16(dst, src) \
    asm volatile("cp.async.cg.shared.global [%0], [%1], 16;" \
                 :: "r"(dst), "l"(src) : "memory")
#define CP_COMMIT() asm volatile("cp.async.commit_group;" ::: "memory")
#define CP_WAIT1()  asm volatile("cp.async.wait_group 1;" ::: "memory")
#define CP_WAIT0()  asm volatile("cp.async.wait_group 0;" ::: "memory")

#define FMA2(d, a, b, c) \
    asm("fma.rn.f32x2 %0, %1, %2, %3;" : "=l"(d) : "l"(a), "l"(b), "l"(c))
#define MUL2(d, a, b) \
    asm("mul.rn.f32x2 %0, %1, %2;" : "=l"(d) : "l"(a), "l"(b))

__device__ __forceinline__ void upk2(unsigned long long v, float& a, float& b) {
    asm("mov.b64 {%0, %1}, %2;" : "=f"(a), "=f"(b) : "l"(v));
}

__global__ __launch_bounds__(THREADS, 1)
void subm_conv_r17(const float* __restrict__ feat,
                   const float* __restrict__ weight,
                   const float* __restrict__ bias,
                   const int* __restrict__ nb,
                   float* __restrict__ out,
                   int N, int total_iters, int totwarps)
{
    extern __shared__ float sm[];
    float2* ws2 = (float2*)sm;

    // Stage weights as fp32 ci-pairs: i = ((g*27 + k)*16 + q)*8 + cp
    for (int i = threadIdx.x; i < 4 * KOFF * 128; i += THREADS) {
        int cp = i & 7;
        int q  = (i >> 3) & 15;
        int gk = i >> 7;                 // g*27 + k
        int g  = gk / KOFF;
        int k  = gk - g * KOFF;
        int ci0 = (q & 7) * 2;
        int co  = 2 * cp + (q >> 3);
        const float* wsrc = weight + ((size_t)gk * 16 + ci0) * 16 + co;
        ws2[g * PGF2 + k * 128 + q * 8 + cp] = make_float2(wsrc[0], wsrc[16]);
    }
    __syncthreads();

    const int lane = threadIdx.x & 31;
    const int wid  = threadIdx.x >> 5;
    const int g    = lane >> 3;          // group
    const int cp   = lane & 7;           // co-pair within group
    const float bx = bias[2 * lane];
    const float by = bias[2 * lane + 1];
    const unsigned long long* wsbase =
        (const unsigned long long*)(ws2 + g * PGF2 + cp);

    float2*   accw  = (float2*)(sm + ACC_F) + wid * (VPW * 32);
    float*    ringw = sm + RING_F + wid * RING_PER_WARP;
    uint32_t* lw    = (uint32_t*)(sm + LIST_F) + wid * LIST_CAP;
    const uint32_t ring_u32 = (uint32_t)__cvta_generic_to_shared(ringw);

    for (int it = blockIdx.x * NWARPS + wid; it < total_iters; it += totwarps) {
        const int vb = it * VPW;
        const int* nbrow = nb + (size_t)vb * KOFF;

        // ---- Phase A: activity mask, prefix scan, emit list (k-major) ----
        // nb is a zero-reuse stream: evict-first so it never displaces feat.
        unsigned am = 0;
        int idx[VPW];
        #pragma unroll
        for (int j = 0; j < VPW; ++j) {
            int v = vb + j;
            int id = (lane < KOFF && v < N) ? __ldcs(&nbrow[j * KOFF + lane])
                                            : -1;
            idx[j] = id;
            am |= (id >= 0 ? 1u : 0u) << j;
        }
        int pc = __popc(am);
        int s = pc;
        #pragma unroll
        for (int d = 1; d < 32; d <<= 1) {
            int t = __shfl_up_sync(FULL, s, d);
            if (lane >= d) s += t;
        }
        const int nb_total = __shfl_sync(FULL, s, 31);
        int pos = s - pc;
        unsigned em = am;
        while (em) {
            int j = __ffs(em) - 1; em &= em - 1;
            lw[pos++] = ((uint32_t)idx[j] << 9) | (uint32_t)(j << 5)
                      | (uint32_t)lane;
        }
        #pragma unroll
        for (int j = 0; j < VPW; ++j)
            accw[j * 32 + lane] = make_float2(bx, by);
        __syncwarp();

        // ---- async fill: wave of 4 bodies, 2 per instruction, LDS-only ----
        auto fill = [&](int wbase, int slotbase) {
            #pragma unroll
            for (int p = 0; p < WAVE; p += 2) {
                int bi = wbase + p + (lane >> 4);
                if (bi < nb_total) {
                    uint32_t ni = lw[bi] >> 9;
                    uint32_t dst = ring_u32
                                 + (uint32_t)(slotbase + p + (lane >> 4)) * 256u
                                 + (uint32_t)(lane & 15) * 16u;
                    const float* src = feat + (size_t)ni * 64 + (lane & 15) * 4;
                    CP_ASYNC16(dst, src);
                }
            }
            CP_COMMIT();
        };

        fill(0, 0);
        fill(WAVE, WAVE);

        // ---- Phase B: dense consume ----
        unsigned long long wx[8], wy[8];
        int kcur = -1;
        for (int wbase = 0; wbase < nb_total; wbase += WAVE) {
            CP_WAIT1();
            __syncwarp();
            const int slotbase = ((wbase >> 2) & 1) * WAVE;
            const int cend = (wbase + WAVE < nb_total) ? wbase + WAVE : nb_total;
            for (int i = wbase; i < cend; ++i) {
                const uint32_t e = lw[i];               // warp-uniform
                const int k = (int)(e & 31u);
                const int j = (int)((e >> 5) & 15u);
                if (k != kcur) {                        // ~1 per 3.66 bodies
                    kcur = k;
                    const unsigned long long* wp = wsbase + k * 128;
                    #pragma unroll
                    for (int q = 0; q < 8; ++q) wx[q] = wp[q * 8];       // LDS.64
                    #pragma unroll
                    for (int q = 0; q < 8; ++q) wy[q] = wp[64 + q * 8];  // LDS.64
                }
                const ulonglong2* sp = (const ulonglong2*)
                    (ringw + (slotbase + (i - wbase)) * 64 + g * 16);
                ulonglong2 p0 = sp[0], p1 = sp[1], p2 = sp[2], p3 = sp[3];
                unsigned long long ax, ay;
                MUL2(ax, p0.x, wx[0]);        MUL2(ay, p0.x, wy[0]);
                FMA2(ax, p0.y, wx[1], ax);    FMA2(ay, p0.y, wy[1], ay);
                FMA2(ax, p1.x, wx[2], ax);    FMA2(ay, p1.x, wy[2], ay);
                FMA2(ax, p1.y, wx[3], ax);    FMA2(ay, p1.y, wy[3], ay);
                FMA2(ax, p2.x, wx[4], ax);    FMA2(ay, p2.x, wy[4], ay);
                FMA2(ax, p2.y, wx[5], ax);    FMA2(ay, p2.y, wy[5], ay);
                FMA2(ax, p3.x, wx[6], ax);    FMA2(ay, p3.x, wy[6], ay);
                FMA2(ax, p3.y, wx[7], ax);    FMA2(ay, p3.y, wy[7], ay);
                float x0, x1, y0, y1;
                upk2(ax, x0, x1);
                upk2(ay, y0, y1);
                float xs = x0 + x1, ys = y0 + y1;
                float2* ap = accw + j * 32 + lane;      // same-lane RMW
                float2 a = *ap;
                a.x += xs; a.y += ys;
                *ap = a;
            }
            fill(wbase + 2 * WAVE, slotbase);
        }
        CP_WAIT0();
        __syncwarp();

        // ---- store 16 voxels x 64 channels, evict-first (write stream) ----
        #pragma unroll
        for (int j = 0; j < VPW; ++j) {
            int v = vb + j;
            if (v < N)
                __stcs(&((float2*)(out + (size_t)v * 64))[lane],
                       accw[j * 32 + lane]);
        }
        __syncwarp();
    }
}

extern "C" void kernel_launch(void* const* d_in, const int* in_sizes, int n_in,
                              void* d_out, int out_size)
{
    const float* feat   = (const float*)d_in[0];  // [N, 64]
    const float* weight = (const float*)d_in[1];  // [4, 27, 16, 16]
    const float* bias   = (const float*)d_in[2];  // [64]
    const int*   nb     = (const int*)d_in[3];    // [N, 27]
    float* out = (float*)d_out;

    int N = in_sizes[0] / 64;

    // Idempotent, enqueues no work; safe under graph capture.
    cudaFuncSetAttribute(subm_conv_r17,
                         cudaFuncAttributeMaxDynamicSharedMemorySize, SMEM_BYTES);

    const int blocks = 152;              // 1 CTA/SM (223.6 KB smem)
    const int totwarps = blocks * NWARPS;
    int total_iters = (N + VPW - 1) / VPW;

    subm_conv_r17<<<blocks, THREADS, SMEM_BYTES>>>(feat, weight, bias, nb,
                                                   out, N, total_iters, totwarps);
    (void)n_in; (void)out_size;
}